// round 15
// baseline (speedup 1.0000x reference)
#include <cuda_runtime.h>

// ---------------------------------------------------------------------------
// MS-SSIM, 4 levels, 11-tap Gaussian (sigma=1.5), VALID padding.
// X, Y: [16, 3, 512, 512] fp32. Output: 16 fp32 (1 - ms_ssim per batch).
//
// R15: algebraic reduction. sigma1^2+sigma2^2 = blur(x^2+y^2) - mu1^2 - mu2^2,
// so only FOUR blurred quantities are needed: (mu1,mu2) and (S,P) with
// S = blur(x^2+y^2), P = blur(x*y). Both pack into f32x2 lanes: every tap
// (horizontal and vertical) is exactly 2 packed FMA slots (was 4 / 3).
// smem holds 16 B/px: (x,y) and (x^2+y^2, x*y), loaded as one LDS.128.
// Tiles: L0/L1 128x10 (44.8 KB, 5 blocks/SM), L2/L3 64x8 (21.9 KB, 10/SM).
// ---------------------------------------------------------------------------

#define KW 11
#define NB 16
#define NC 3

__device__ double g_acc[4 * NB];
__device__ float g_X1[NB * NC * 256 * 256];
__device__ float g_Y1[NB * NC * 256 * 256];
__device__ float g_X2[NB * NC * 128 * 128];
__device__ float g_Y2[NB * NC * 128 * 128];
__device__ float g_X3[NB * NC * 64 * 64];
__device__ float g_Y3[NB * NC * 64 * 64];

typedef unsigned long long ull;

__device__ __forceinline__ ull pk2(float lo, float hi) {
    ull r; asm("mov.b64 %0,{%1,%2};" : "=l"(r) : "f"(lo), "f"(hi)); return r;
}
__device__ __forceinline__ void up2(ull v, float& lo, float& hi) {
    asm("mov.b64 {%0,%1},%2;" : "=f"(lo), "=f"(hi) : "l"(v));
}
__device__ __forceinline__ ull fma2(ull a, ull b, ull c) {
    ull d; asm("fma.rn.f32x2 %0,%1,%2,%3;" : "=l"(d) : "l"(a), "l"(b), "l"(c));
    return d;
}
__device__ __forceinline__ ull mul2(ull a, ull b) {
    ull d; asm("mul.rn.f32x2 %0,%1,%2;" : "=l"(d) : "l"(a), "l"(b));
    return d;
}

__global__ void zero_acc_kernel() {
    int i = threadIdx.x;
    if (i < 4 * NB) g_acc[i] = 0.0;
}

// ---------------------------------------------------------------------------
// Per-level SSIM kernel. Packed quantities:
//   .x lane-pair = (x, y)          -> mu accumulation
//   .y lane-pair = (x^2+y^2, x*y)  -> S,P accumulation
// POOL: fused 2x2 avg-pool; last tile row pools all remaining rows.
// Grid: (tilesX*tilesY, NC, NB), block: TW_ threads.
// ---------------------------------------------------------------------------
template<int TW_, int TH_, bool LAST, bool POOL, int MINB>
__global__ __launch_bounds__(TW_, MINB) void ssim_level_kernel(
    const float* __restrict__ X, const float* __restrict__ Y,
    float* __restrict__ Xp, float* __restrict__ Yp,
    int H, int W, int outH, int outW, int tilesX, int level)
{
    constexpr int IH_  = TH_ + KW - 1;
    constexpr int IW_  = TW_ + KW - 1;
    constexpr int IWP_ = TW_ + 12;
    constexpr int NWARP = TW_ / 32;

    __shared__ ulonglong2 sxy[IH_][IWP_];
    __shared__ float red[NWARP];

    const int b = blockIdx.z;
    const int c = blockIdx.y;
    const int tile = blockIdx.x;
    const int tx = tile % tilesX;
    const int ty = tile / tilesX;
    const int ix0 = tx * TW_;
    const int iy0 = ty * TH_;
    const int tid = threadIdx.x;

    const size_t plane = (size_t)(b * NC + c) * H * W;
    const float* __restrict__ Xi = X + plane;
    const float* __restrict__ Yi = Y + plane;

    // ---- Phase 0: halo load + per-pixel (x^2+y^2, x*y) precompute ----
    #pragma unroll 2
    for (int i = tid; i < IH_ * IW_; i += TW_) {
        int r  = i / IW_;
        int cc = i - r * IW_;
        int gy = min(iy0 + r,  H - 1);
        int gx = min(ix0 + cc, W - 1);
        int gi = gy * W + gx;
        float xv = Xi[gi];
        float yv = Yi[gi];
        float ss = fmaf(xv, xv, yv * yv);
        float pp = xv * yv;
        sxy[r][cc] = make_ulonglong2(pk2(xv, yv), pk2(ss, pp));
    }
    __syncthreads();

    const float G[KW] = {
        0.00102838f, 0.00759875f, 0.03600077f, 0.10936069f, 0.21300553f,
        0.26601174f,
        0.21300553f, 0.10936069f, 0.03600077f, 0.00759875f, 0.00102838f
    };
    const float C1 = 1e-4f;
    const float C2 = 9e-4f;

    ull r01[KW];   // ring: (blur_h x, blur_h y)
    ull rq[KW];    // ring: (blur_h (x^2+y^2), blur_h (x*y))

    const int lx = tid;
    const int ox = ix0 + lx;
    const bool colOK = (ox < outW);
    float local = 0.f;

    #pragma unroll
    for (int r = 0; r < IH_; r++) {
        const ulonglong2* __restrict__ row = &sxy[r][lx];
        ull s01, sq;
        {
            ulonglong2 v = row[0];
            ull gg = pk2(G[0], G[0]);
            s01 = mul2(gg, v.x);
            sq  = mul2(gg, v.y);
        }
        #pragma unroll
        for (int k = 1; k < KW; k++) {
            ulonglong2 v = row[k];
            ull gg = pk2(G[k], G[k]);
            s01 = fma2(gg, v.x, s01);
            sq  = fma2(gg, v.y, sq);
        }
        r01[r % KW] = s01;
        rq[r % KW]  = sq;

        if (r >= KW - 1) {
            const int orow = r - (KW - 1);
            ull m01, mq;
            {
                int idx = orow % KW;
                ull gg = pk2(G[0], G[0]);
                m01 = mul2(gg, r01[idx]);
                mq  = mul2(gg, rq[idx]);
            }
            #pragma unroll
            for (int k = 1; k < KW; k++) {
                int idx = (orow + k) % KW;
                ull gg = pk2(G[k], G[k]);
                m01 = fma2(gg, r01[idx], m01);
                mq  = fma2(gg, rq[idx], mq);
            }
            int oy = iy0 + orow;
            if (colOK && oy < outH) {
                float mu1, mu2, S, P;
                up2(m01, mu1, mu2);
                up2(mq,  S,   P);
                float mu11 = mu1 * mu1;
                float mu22 = mu2 * mu2;
                float mu12 = mu1 * mu2;
                float s12  = P - mu12;
                float sden = S - mu11 - mu22;
                float cs = __fdividef(2.f * s12 + C2, sden + C2);
                cs = fmaxf(cs, 0.f);
                if (LAST) {
                    float lum = __fdividef(2.f * mu12 + C1,
                                           mu11 + mu22 + C1);
                    local = fmaf(lum, cs, local);
                } else {
                    local += cs;
                }
            }
        }
    }

    // ---- Fused 2x2 pool. Last tile row pools all remaining rows (<= IH_).
    if (POOL) {
        const int oW = W >> 1;
        const int oHp = H >> 1;
        const int pgy0 = iy0 >> 1;
        const int pgx0 = ix0 >> 1;
        constexpr int PW = TW_ / 2;
        const int tilesY = (int)(gridDim.x) / tilesX;
        const int nin = (ty == tilesY - 1) ? (H - iy0) : TH_;
        const int npool = nin >> 1;
        float* __restrict__ Xo = Xp + (size_t)(b * NC + c) * oW * oHp;
        float* __restrict__ Yo = Yp + (size_t)(b * NC + c) * oW * oHp;
        for (int idx = tid; idx < npool * PW; idx += TW_) {
            int py = idx / PW;
            int px = idx % PW;
            float x00, y00, x01, y01, x10, y10, x11, y11;
            up2(sxy[2 * py][2 * px].x,     x00, y00);
            up2(sxy[2 * py][2 * px + 1].x, x01, y01);
            up2(sxy[2 * py + 1][2 * px].x,     x10, y10);
            up2(sxy[2 * py + 1][2 * px + 1].x, x11, y11);
            float xv = 0.25f * ((x00 + x01) + (x10 + x11));
            float yv = 0.25f * ((y00 + y01) + (y10 + y11));
            size_t o = (size_t)(pgy0 + py) * oW + (pgx0 + px);
            Xo[o] = xv;
            Yo[o] = yv;
        }
    }

    #pragma unroll
    for (int s = 16; s > 0; s >>= 1)
        local += __shfl_down_sync(0xffffffffu, local, s);
    if ((tid & 31) == 0) red[tid >> 5] = local;
    __syncthreads();
    if (tid == 0) {
        float t = 0.f;
        #pragma unroll
        for (int w = 0; w < NWARP; w++) t += red[w];
        atomicAdd(&g_acc[level * NB + b], (double)t);
    }
}

__global__ void finalize_kernel(float* __restrict__ out) {
    int b = threadIdx.x;
    if (b >= NB) return;
    const double counts[4] = {
        3.0 * 502.0 * 502.0,
        3.0 * 246.0 * 246.0,
        3.0 * 118.0 * 118.0,
        3.0 * 54.0  * 54.0
    };
    const double wraw[4] = {0.0448, 0.2856, 0.3001, 0.2363};
    const double wsum = 0.0448 + 0.2856 + 0.3001 + 0.2363;
    double s = 0.0;
    #pragma unroll
    for (int l = 0; l < 4; l++) {
        double v = g_acc[l * NB + b] / counts[l];
        v = v > 1e-8 ? v : 1e-8;
        s += (wraw[l] / wsum) * log(v);
    }
    out[b] = (float)(1.0 - exp(s));
}

extern "C" void kernel_launch(void* const* d_in, const int* in_sizes, int n_in,
                              void* d_out, int out_size)
{
    const float* X = (const float*)d_in[0];
    const float* Y = (const float*)d_in[1];
    float* out = (float*)d_out;
    (void)in_sizes; (void)n_in; (void)out_size;

    static float *pX1 = nullptr, *pY1 = nullptr, *pX2 = nullptr, *pY2 = nullptr,
                 *pX3 = nullptr, *pY3 = nullptr;
    if (!pX1) {
        cudaGetSymbolAddress((void**)&pX1, g_X1);
        cudaGetSymbolAddress((void**)&pY1, g_Y1);
        cudaGetSymbolAddress((void**)&pX2, g_X2);
        cudaGetSymbolAddress((void**)&pY2, g_Y2);
        cudaGetSymbolAddress((void**)&pX3, g_X3);
        cudaGetSymbolAddress((void**)&pY3, g_Y3);
    }

    zero_acc_kernel<<<1, 64>>>();

    // Level 0: 512 -> out 502, fused pool to 256. Tiles 128x10, 5 blocks/SM.
    {
        dim3 grid(4 * 51, NC, NB);     // tilesX=4, tilesY=51 (51*10=510)
        ssim_level_kernel<128, 10, false, true, 5><<<grid, 128>>>(
            X, Y, pX1, pY1, 512, 512, 502, 502, 4, 0);
    }
    // Level 1: 256 -> out 246, fused pool to 128. Tiles 128x10.
    {
        dim3 grid(2 * 25, NC, NB);     // tilesX=2, tilesY=25 (25*10=250)
        ssim_level_kernel<128, 10, false, true, 5><<<grid, 128>>>(
            pX1, pY1, pX2, pY2, 256, 256, 246, 246, 2, 1);
    }
    // Level 2: 128 -> out 118, fused pool to 64. Tiles 64x8, 10 blocks/SM.
    {
        dim3 grid(2 * 15, NC, NB);     // tilesX=2, tilesY=15 (15*8=120)
        ssim_level_kernel<64, 8, false, true, 10><<<grid, 64>>>(
            pX2, pY2, pX3, pY3, 128, 128, 118, 118, 2, 2);
    }
    // Level 3: 64 -> out 54, last (ssim map), no pool. Tiles 64x8.
    {
        dim3 grid(1 * 7, NC, NB);      // tilesY=7 (7*8=56)
        ssim_level_kernel<64, 8, true, false, 10><<<grid, 64>>>(
            pX3, pY3, nullptr, nullptr, 64, 64, 54, 54, 1, 3);
    }

    finalize_kernel<<<1, 32>>>(out);
}

// round 16
// speedup vs baseline: 1.5196x; 1.5196x over previous
#include <cuda_runtime.h>

// ---------------------------------------------------------------------------
// MS-SSIM, 4 levels, 11-tap Gaussian (sigma=1.5), VALID padding.
// X, Y: [16, 3, 512, 512] fp32. Output: 16 fp32 (1 - ms_ssim per batch).
//
// R16: R14 champion (8 B/px smem, 4-slot taps, L0/L1 128x22 @5 blocks/SM,
// L2/L3 64x16 @MINB=12) + 2-way SPLIT ACCUMULATORS in both the horizontal
// and vertical tap loops: ~7 independent FMA chains per thread instead of
// ~3, so each warp can keep the FMA pipe fed at fixed occupancy.
// ---------------------------------------------------------------------------

#define KW 11
#define NB 16
#define NC 3

__device__ double g_acc[4 * NB];
__device__ float g_X1[NB * NC * 256 * 256];
__device__ float g_Y1[NB * NC * 256 * 256];
__device__ float g_X2[NB * NC * 128 * 128];
__device__ float g_Y2[NB * NC * 128 * 128];
__device__ float g_X3[NB * NC * 64 * 64];
__device__ float g_Y3[NB * NC * 64 * 64];

typedef unsigned long long ull;

__device__ __forceinline__ ull pk2(float lo, float hi) {
    ull r; asm("mov.b64 %0,{%1,%2};" : "=l"(r) : "f"(lo), "f"(hi)); return r;
}
__device__ __forceinline__ void up2(ull v, float& lo, float& hi) {
    asm("mov.b64 {%0,%1},%2;" : "=f"(lo), "=f"(hi) : "l"(v));
}
__device__ __forceinline__ ull fma2(ull a, ull b, ull c) {
    ull d; asm("fma.rn.f32x2 %0,%1,%2,%3;" : "=l"(d) : "l"(a), "l"(b), "l"(c));
    return d;
}
__device__ __forceinline__ ull mul2(ull a, ull b) {
    ull d; asm("mul.rn.f32x2 %0,%1,%2;" : "=l"(d) : "l"(a), "l"(b));
    return d;
}
__device__ __forceinline__ ull add2(ull a, ull b) {
    ull d; asm("add.rn.f32x2 %0,%1,%2;" : "=l"(d) : "l"(a), "l"(b));
    return d;
}

__global__ void zero_acc_kernel() {
    int i = threadIdx.x;
    if (i < 4 * NB) g_acc[i] = 0.0;
}

// ---------------------------------------------------------------------------
// Per-level SSIM kernel. POOL: fused 2x2 avg-pool; last tile row pools all
// remaining rows. Grid: (tilesX*tilesY, NC, NB), block: TW_ threads.
// ---------------------------------------------------------------------------
template<int TW_, int TH_, bool LAST, bool POOL, int MINB>
__global__ __launch_bounds__(TW_, MINB) void ssim_level_kernel(
    const float* __restrict__ X, const float* __restrict__ Y,
    float* __restrict__ Xp, float* __restrict__ Yp,
    int H, int W, int outH, int outW, int tilesX, int level)
{
    constexpr int IH_  = TH_ + KW - 1;
    constexpr int IW_  = TW_ + KW - 1;
    constexpr int IWP_ = TW_ + 10;
    constexpr int NWARP = TW_ / 32;

    __shared__ float2 sxy[IH_][IWP_];
    __shared__ float red[NWARP];

    const int b = blockIdx.z;
    const int c = blockIdx.y;
    const int tile = blockIdx.x;
    const int tx = tile % tilesX;
    const int ty = tile / tilesX;
    const int ix0 = tx * TW_;
    const int iy0 = ty * TH_;
    const int tid = threadIdx.x;

    const size_t plane = (size_t)(b * NC + c) * H * W;
    const float* __restrict__ Xi = X + plane;
    const float* __restrict__ Yi = Y + plane;

    // ---- Phase 0: cooperative halo load (clamped) ----
    #pragma unroll 4
    for (int i = tid; i < IH_ * IW_; i += TW_) {
        int r  = i / IW_;
        int cc = i - r * IW_;
        int gy = min(iy0 + r,  H - 1);
        int gx = min(ix0 + cc, W - 1);
        int gi = gy * W + gx;
        sxy[r][cc] = make_float2(Xi[gi], Yi[gi]);
    }
    __syncthreads();

    const float G[KW] = {
        0.00102838f, 0.00759875f, 0.03600077f, 0.10936069f, 0.21300553f,
        0.26601174f,
        0.21300553f, 0.10936069f, 0.03600077f, 0.00759875f, 0.00102838f
    };
    const float C1 = 1e-4f;
    const float C2 = 9e-4f;

    ull   r01[KW];
    ull   r23[KW];
    float r4[KW];

    const int lx = tid;
    const int ox = ix0 + lx;
    const bool colOK = (ox < outW);
    float local = 0.f;

    #pragma unroll
    for (int r = 0; r < IH_; r++) {
        const ull* __restrict__ row =
            reinterpret_cast<const ull*>(&sxy[r][lx]);

        // Horizontal 11 taps with 2-way split accumulators (even/odd k).
        ull s01a, s23a; float s4a;
        ull s01b, s23b; float s4b;
        {
            ull v = row[0];
            ull gg = pk2(G[0], G[0]);
            s01a = mul2(gg, v);
            ull t = mul2(gg, v);
            s23a = mul2(t, v);
            float xv, yv, tl, th;
            up2(v, xv, yv); up2(t, tl, th);
            s4a = tl * yv;
            (void)xv; (void)th;
        }
        {
            ull v = row[1];
            ull gg = pk2(G[1], G[1]);
            s01b = mul2(gg, v);
            ull t = mul2(gg, v);
            s23b = mul2(t, v);
            float xv, yv, tl, th;
            up2(v, xv, yv); up2(t, tl, th);
            s4b = tl * yv;
            (void)xv; (void)th;
        }
        #pragma unroll
        for (int k = 2; k < KW; k += 2) {
            ull v = row[k];
            ull gg = pk2(G[k], G[k]);
            s01a = fma2(gg, v, s01a);
            ull t = mul2(gg, v);
            s23a = fma2(t, v, s23a);
            float xv, yv, tl, th;
            up2(v, xv, yv); up2(t, tl, th);
            s4a = fmaf(tl, yv, s4a);
            (void)xv; (void)th;
        }
        #pragma unroll
        for (int k = 3; k < KW; k += 2) {
            ull v = row[k];
            ull gg = pk2(G[k], G[k]);
            s01b = fma2(gg, v, s01b);
            ull t = mul2(gg, v);
            s23b = fma2(t, v, s23b);
            float xv, yv, tl, th;
            up2(v, xv, yv); up2(t, tl, th);
            s4b = fmaf(tl, yv, s4b);
            (void)xv; (void)th;
        }
        r01[r % KW] = add2(s01a, s01b);
        r23[r % KW] = add2(s23a, s23b);
        r4[r % KW]  = s4a + s4b;

        if (r >= KW - 1) {
            const int orow = r - (KW - 1);
            // Vertical 11 taps with 2-way split accumulators.
            ull m01a, m23a; float m4a;
            ull m01b, m23b; float m4b;
            {
                int idx = orow % KW;
                ull gg = pk2(G[0], G[0]);
                m01a = mul2(gg, r01[idx]);
                m23a = mul2(gg, r23[idx]);
                m4a  = G[0] * r4[idx];
            }
            {
                int idx = (orow + 1) % KW;
                ull gg = pk2(G[1], G[1]);
                m01b = mul2(gg, r01[idx]);
                m23b = mul2(gg, r23[idx]);
                m4b  = G[1] * r4[idx];
            }
            #pragma unroll
            for (int k = 2; k < KW; k += 2) {
                int idx = (orow + k) % KW;
                ull gg = pk2(G[k], G[k]);
                m01a = fma2(gg, r01[idx], m01a);
                m23a = fma2(gg, r23[idx], m23a);
                m4a  = fmaf(G[k], r4[idx], m4a);
            }
            #pragma unroll
            for (int k = 3; k < KW; k += 2) {
                int idx = (orow + k) % KW;
                ull gg = pk2(G[k], G[k]);
                m01b = fma2(gg, r01[idx], m01b);
                m23b = fma2(gg, r23[idx], m23b);
                m4b  = fmaf(G[k], r4[idx], m4b);
            }
            ull m01 = add2(m01a, m01b);
            ull m23 = add2(m23a, m23b);
            float m4 = m4a + m4b;

            int oy = iy0 + orow;
            if (colOK && oy < outH) {
                float mu1, mu2, xx, yy;
                up2(m01, mu1, mu2);
                up2(m23, xx, yy);
                float s1q = xx - mu1 * mu1;
                float s2q = yy - mu2 * mu2;
                float s12 = m4 - mu1 * mu2;
                float cs = __fdividef(2.f * s12 + C2, s1q + s2q + C2);
                cs = fmaxf(cs, 0.f);
                if (LAST) {
                    float lum = __fdividef(2.f * mu1 * mu2 + C1,
                                           mu1 * mu1 + mu2 * mu2 + C1);
                    local = fmaf(lum, cs, local);
                } else {
                    local += cs;
                }
            }
        }
    }

    // ---- Fused 2x2 pool. Last tile row pools all remaining rows (<= IH_).
    if (POOL) {
        const int oW = W >> 1;
        const int oHp = H >> 1;
        const int pgy0 = iy0 >> 1;
        const int pgx0 = ix0 >> 1;
        constexpr int PW = TW_ / 2;
        const int tilesY = (int)(gridDim.x) / tilesX;
        const int nin = (ty == tilesY - 1) ? (H - iy0) : TH_;
        const int npool = nin >> 1;
        float* __restrict__ Xo = Xp + (size_t)(b * NC + c) * oW * oHp;
        float* __restrict__ Yo = Yp + (size_t)(b * NC + c) * oW * oHp;
        for (int idx = tid; idx < npool * PW; idx += TW_) {
            int py = idx / PW;
            int px = idx % PW;
            float2 a  = sxy[2 * py][2 * px];
            float2 bb = sxy[2 * py][2 * px + 1];
            float2 cc = sxy[2 * py + 1][2 * px];
            float2 dd = sxy[2 * py + 1][2 * px + 1];
            float xv = 0.25f * ((a.x + bb.x) + (cc.x + dd.x));
            float yv = 0.25f * ((a.y + bb.y) + (cc.y + dd.y));
            size_t o = (size_t)(pgy0 + py) * oW + (pgx0 + px);
            Xo[o] = xv;
            Yo[o] = yv;
        }
    }

    #pragma unroll
    for (int s = 16; s > 0; s >>= 1)
        local += __shfl_down_sync(0xffffffffu, local, s);
    if ((tid & 31) == 0) red[tid >> 5] = local;
    __syncthreads();
    if (tid == 0) {
        float t = 0.f;
        #pragma unroll
        for (int w = 0; w < NWARP; w++) t += red[w];
        atomicAdd(&g_acc[level * NB + b], (double)t);
    }
}

__global__ void finalize_kernel(float* __restrict__ out) {
    int b = threadIdx.x;
    if (b >= NB) return;
    const double counts[4] = {
        3.0 * 502.0 * 502.0,
        3.0 * 246.0 * 246.0,
        3.0 * 118.0 * 118.0,
        3.0 * 54.0  * 54.0
    };
    const double wraw[4] = {0.0448, 0.2856, 0.3001, 0.2363};
    const double wsum = 0.0448 + 0.2856 + 0.3001 + 0.2363;
    double s = 0.0;
    #pragma unroll
    for (int l = 0; l < 4; l++) {
        double v = g_acc[l * NB + b] / counts[l];
        v = v > 1e-8 ? v : 1e-8;
        s += (wraw[l] / wsum) * log(v);
    }
    out[b] = (float)(1.0 - exp(s));
}

extern "C" void kernel_launch(void* const* d_in, const int* in_sizes, int n_in,
                              void* d_out, int out_size)
{
    const float* X = (const float*)d_in[0];
    const float* Y = (const float*)d_in[1];
    float* out = (float*)d_out;
    (void)in_sizes; (void)n_in; (void)out_size;

    static float *pX1 = nullptr, *pY1 = nullptr, *pX2 = nullptr, *pY2 = nullptr,
                 *pX3 = nullptr, *pY3 = nullptr;
    if (!pX1) {
        cudaGetSymbolAddress((void**)&pX1, g_X1);
        cudaGetSymbolAddress((void**)&pY1, g_Y1);
        cudaGetSymbolAddress((void**)&pX2, g_X2);
        cudaGetSymbolAddress((void**)&pY2, g_Y2);
        cudaGetSymbolAddress((void**)&pX3, g_X3);
        cudaGetSymbolAddress((void**)&pY3, g_Y3);
    }

    zero_acc_kernel<<<1, 64>>>();

    // Level 0: 512 -> out 502, fused pool to 256. Tiles 128x22 (5 blocks/SM).
    {
        dim3 grid(4 * 23, NC, NB);
        ssim_level_kernel<128, 22, false, true, 5><<<grid, 128>>>(
            X, Y, pX1, pY1, 512, 512, 502, 502, 4, 0);
    }
    // Level 1: 256 -> out 246, fused pool to 128. Tiles 128x22.
    {
        dim3 grid(2 * 12, NC, NB);
        ssim_level_kernel<128, 22, false, true, 5><<<grid, 128>>>(
            pX1, pY1, pX2, pY2, 256, 256, 246, 246, 2, 1);
    }
    // Level 2: 128 -> out 118, fused pool to 64. Tiles 64x16, MINB=12.
    {
        dim3 grid(2 * 8, NC, NB);
        ssim_level_kernel<64, 16, false, true, 12><<<grid, 64>>>(
            pX2, pY2, pX3, pY3, 128, 128, 118, 118, 2, 2);
    }
    // Level 3: 64 -> out 54, last (ssim map), no pool. Tiles 64x16, MINB=12.
    {
        dim3 grid(1 * 4, NC, NB);
        ssim_level_kernel<64, 16, true, false, 12><<<grid, 64>>>(
            pX3, pY3, nullptr, nullptr, 64, 64, 54, 54, 1, 3);
    }

    finalize_kernel<<<1, 32>>>(out);
}

// round 17
// speedup vs baseline: 1.6864x; 1.1098x over previous
#include <cuda_runtime.h>

// ---------------------------------------------------------------------------
// MS-SSIM, 4 levels, 11-tap Gaussian (sigma=1.5), VALID padding.
// X, Y: [16, 3, 512, 512] fp32. Output: 16 fp32 (1 - ms_ssim per batch).
//
// R17: I$-aware restructure. IH is a multiple of 11 (L0/L1: 23+10=33,
// L2/L3: 12+10=22); row loop = outer rb (NOT unrolled) x inner ri (unrolled
// 11). Ring indices become compile-time constants (slot=ri, vertical tap
// (ri+1+k)%11), code size drops ~3x to fit L1.5 I$, ring-index ALU vanishes.
// Tap bodies = R14's proven 4-slot packed form. Fused pool handles odd TH
// via even-aligned global row pairs.
// ---------------------------------------------------------------------------

#define KW 11
#define NB 16
#define NC 3

__device__ double g_acc[4 * NB];
__device__ float g_X1[NB * NC * 256 * 256];
__device__ float g_Y1[NB * NC * 256 * 256];
__device__ float g_X2[NB * NC * 128 * 128];
__device__ float g_Y2[NB * NC * 128 * 128];
__device__ float g_X3[NB * NC * 64 * 64];
__device__ float g_Y3[NB * NC * 64 * 64];

typedef unsigned long long ull;

__device__ __forceinline__ ull pk2(float lo, float hi) {
    ull r; asm("mov.b64 %0,{%1,%2};" : "=l"(r) : "f"(lo), "f"(hi)); return r;
}
__device__ __forceinline__ void up2(ull v, float& lo, float& hi) {
    asm("mov.b64 {%0,%1},%2;" : "=f"(lo), "=f"(hi) : "l"(v));
}
__device__ __forceinline__ ull fma2(ull a, ull b, ull c) {
    ull d; asm("fma.rn.f32x2 %0,%1,%2,%3;" : "=l"(d) : "l"(a), "l"(b), "l"(c));
    return d;
}
__device__ __forceinline__ ull mul2(ull a, ull b) {
    ull d; asm("mul.rn.f32x2 %0,%1,%2;" : "=l"(d) : "l"(a), "l"(b));
    return d;
}

__global__ void zero_acc_kernel() {
    int i = threadIdx.x;
    if (i < 4 * NB) g_acc[i] = 0.0;
}

// ---------------------------------------------------------------------------
// Per-level SSIM kernel. IH_ must be a multiple of 11.
// Grid: (tilesX*tilesY, NC, NB), block: TW_ threads.
// ---------------------------------------------------------------------------
template<int TW_, int TH_, bool LAST, bool POOL, int MINB>
__global__ __launch_bounds__(TW_, MINB) void ssim_level_kernel(
    const float* __restrict__ X, const float* __restrict__ Y,
    float* __restrict__ Xp, float* __restrict__ Yp,
    int H, int W, int outH, int outW, int tilesX, int level)
{
    constexpr int IH_  = TH_ + KW - 1;
    static_assert(IH_ % 11 == 0, "IH must be a multiple of 11");
    constexpr int NRB  = IH_ / 11;
    constexpr int IW_  = TW_ + KW - 1;
    constexpr int IWP_ = TW_ + 10;
    constexpr int NWARP = TW_ / 32;

    __shared__ float2 sxy[IH_][IWP_];
    __shared__ float red[NWARP];

    const int b = blockIdx.z;
    const int c = blockIdx.y;
    const int tile = blockIdx.x;
    const int tx = tile % tilesX;
    const int ty = tile / tilesX;
    const int ix0 = tx * TW_;
    const int iy0 = ty * TH_;
    const int tid = threadIdx.x;

    const size_t plane = (size_t)(b * NC + c) * H * W;
    const float* __restrict__ Xi = X + plane;
    const float* __restrict__ Yi = Y + plane;

    // ---- Phase 0: cooperative halo load (clamped) ----
    #pragma unroll 4
    for (int i = tid; i < IH_ * IW_; i += TW_) {
        int r  = i / IW_;
        int cc = i - r * IW_;
        int gy = min(iy0 + r,  H - 1);
        int gx = min(ix0 + cc, W - 1);
        int gi = gy * W + gx;
        sxy[r][cc] = make_float2(Xi[gi], Yi[gi]);
    }
    __syncthreads();

    const float G[KW] = {
        0.00102838f, 0.00759875f, 0.03600077f, 0.10936069f, 0.21300553f,
        0.26601174f,
        0.21300553f, 0.10936069f, 0.03600077f, 0.00759875f, 0.00102838f
    };
    const float C1 = 1e-4f;
    const float C2 = 9e-4f;

    ull   r01[KW];
    ull   r23[KW];
    float r4[KW];

    const int lx = tid;
    const int ox = ix0 + lx;
    const bool colOK = (ox < outW);
    float local = 0.f;

    #pragma unroll 1
    for (int rb = 0; rb < NRB; rb++) {
        #pragma unroll
        for (int ri = 0; ri < 11; ri++) {
            const int r = rb * 11 + ri;
            const ull* __restrict__ row =
                reinterpret_cast<const ull*>(&sxy[r][lx]);
            // Horizontal 11 taps -> ring slot ri (compile-time).
            ull s01, s23; float s4;
            {
                ull v = row[0];
                ull gg = pk2(G[0], G[0]);
                s01 = mul2(gg, v);
                ull t = mul2(gg, v);
                s23 = mul2(t, v);
                float xv, yv, tl, th;
                up2(v, xv, yv); up2(t, tl, th);
                s4 = tl * yv;
                (void)xv; (void)th;
            }
            #pragma unroll
            for (int k = 1; k < KW; k++) {
                ull v = row[k];
                ull gg = pk2(G[k], G[k]);
                s01 = fma2(gg, v, s01);
                ull t = mul2(gg, v);
                s23 = fma2(t, v, s23);
                float xv, yv, tl, th;
                up2(v, xv, yv); up2(t, tl, th);
                s4 = fmaf(tl, yv, s4);
                (void)xv; (void)th;
            }
            r01[ri] = s01;
            r23[ri] = s23;
            r4[ri]  = s4;

            // Vertical pass once the ring is full (r >= 10).
            if (rb > 0 || ri == 10) {
                // Ring index for tap k: (ri+1+k) % 11 — compile-time.
                ull m01, m23; float m4;
                {
                    constexpr int kk = 0;
                    const int idx0 = (ri + 1 + kk) % 11;
                    ull gg = pk2(G[0], G[0]);
                    m01 = mul2(gg, r01[idx0]);
                    m23 = mul2(gg, r23[idx0]);
                    m4  = G[0] * r4[idx0];
                }
                #pragma unroll
                for (int k = 1; k < KW; k++) {
                    const int idx = (ri + 1 + k) % 11;
                    ull gg = pk2(G[k], G[k]);
                    m01 = fma2(gg, r01[idx], m01);
                    m23 = fma2(gg, r23[idx], m23);
                    m4  = fmaf(G[k], r4[idx], m4);
                }
                int oy = iy0 + r - (KW - 1);
                if (colOK && oy < outH) {
                    float mu1, mu2, xx, yy;
                    up2(m01, mu1, mu2);
                    up2(m23, xx, yy);
                    float s1q = xx - mu1 * mu1;
                    float s2q = yy - mu2 * mu2;
                    float s12 = m4 - mu1 * mu2;
                    float cs = __fdividef(2.f * s12 + C2, s1q + s2q + C2);
                    cs = fmaxf(cs, 0.f);
                    if (LAST) {
                        float lum = __fdividef(2.f * mu1 * mu2 + C1,
                                               mu1 * mu1 + mu2 * mu2 + C1);
                        local = fmaf(lum, cs, local);
                    } else {
                        local += cs;
                    }
                }
            }
        }
    }

    // ---- Fused 2x2 pool: even-aligned global pairs owned by this tile ----
    if (POOL) {
        const int oW = W >> 1;
        const int oHp = H >> 1;
        const int tilesY = (int)(gridDim.x) / tilesX;
        const int pgx0 = ix0 >> 1;
        constexpr int PW = TW_ / 2;
        // pairs p with 2p in [iy0, iy0+TH); last tile extends to H.
        const int pstart = (iy0 + 1) >> 1;
        const int pend   = (ty == tilesY - 1) ? oHp : ((iy0 + TH_ + 1) >> 1);
        const int npool  = pend - pstart;
        float* __restrict__ Xo = Xp + (size_t)(b * NC + c) * oW * oHp;
        float* __restrict__ Yo = Yp + (size_t)(b * NC + c) * oW * oHp;
        for (int idx = tid; idx < npool * PW; idx += TW_) {
            int py = idx / PW;
            int px = idx % PW;
            int lr = (pstart + py) * 2 - iy0;   // local row in smem
            float2 a  = sxy[lr][2 * px];
            float2 bb = sxy[lr][2 * px + 1];
            float2 cc = sxy[lr + 1][2 * px];
            float2 dd = sxy[lr + 1][2 * px + 1];
            float xv = 0.25f * ((a.x + bb.x) + (cc.x + dd.x));
            float yv = 0.25f * ((a.y + bb.y) + (cc.y + dd.y));
            size_t o = (size_t)(pstart + py) * oW + (pgx0 + px);
            Xo[o] = xv;
            Yo[o] = yv;
        }
    }

    #pragma unroll
    for (int s = 16; s > 0; s >>= 1)
        local += __shfl_down_sync(0xffffffffu, local, s);
    if ((tid & 31) == 0) red[tid >> 5] = local;
    __syncthreads();
    if (tid == 0) {
        float t = 0.f;
        #pragma unroll
        for (int w = 0; w < NWARP; w++) t += red[w];
        atomicAdd(&g_acc[level * NB + b], (double)t);
    }
}

__global__ void finalize_kernel(float* __restrict__ out) {
    int b = threadIdx.x;
    if (b >= NB) return;
    const double counts[4] = {
        3.0 * 502.0 * 502.0,
        3.0 * 246.0 * 246.0,
        3.0 * 118.0 * 118.0,
        3.0 * 54.0  * 54.0
    };
    const double wraw[4] = {0.0448, 0.2856, 0.3001, 0.2363};
    const double wsum = 0.0448 + 0.2856 + 0.3001 + 0.2363;
    double s = 0.0;
    #pragma unroll
    for (int l = 0; l < 4; l++) {
        double v = g_acc[l * NB + b] / counts[l];
        v = v > 1e-8 ? v : 1e-8;
        s += (wraw[l] / wsum) * log(v);
    }
    out[b] = (float)(1.0 - exp(s));
}

extern "C" void kernel_launch(void* const* d_in, const int* in_sizes, int n_in,
                              void* d_out, int out_size)
{
    const float* X = (const float*)d_in[0];
    const float* Y = (const float*)d_in[1];
    float* out = (float*)d_out;
    (void)in_sizes; (void)n_in; (void)out_size;

    static float *pX1 = nullptr, *pY1 = nullptr, *pX2 = nullptr, *pY2 = nullptr,
                 *pX3 = nullptr, *pY3 = nullptr;
    if (!pX1) {
        cudaGetSymbolAddress((void**)&pX1, g_X1);
        cudaGetSymbolAddress((void**)&pY1, g_Y1);
        cudaGetSymbolAddress((void**)&pX2, g_X2);
        cudaGetSymbolAddress((void**)&pY2, g_Y2);
        cudaGetSymbolAddress((void**)&pX3, g_X3);
        cudaGetSymbolAddress((void**)&pY3, g_Y3);
    }

    zero_acc_kernel<<<1, 64>>>();

    // Level 0: 512 -> out 502, fused pool to 256. Tiles 128x23 (IH=33),
    // smem 36.4KB -> 5 blocks/SM.
    {
        dim3 grid(4 * 22, NC, NB);     // tilesY=22 (22*23=506)
        ssim_level_kernel<128, 23, false, true, 5><<<grid, 128>>>(
            X, Y, pX1, pY1, 512, 512, 502, 502, 4, 0);
    }
    // Level 1: 256 -> out 246, fused pool to 128. Tiles 128x23.
    {
        dim3 grid(2 * 11, NC, NB);     // tilesY=11 (11*23=253)
        ssim_level_kernel<128, 23, false, true, 5><<<grid, 128>>>(
            pX1, pY1, pX2, pY2, 256, 256, 246, 246, 2, 1);
    }
    // Level 2: 128 -> out 118, fused pool to 64. Tiles 64x12 (IH=22).
    {
        dim3 grid(2 * 10, NC, NB);     // tilesY=10 (10*12=120)
        ssim_level_kernel<64, 12, false, true, 12><<<grid, 64>>>(
            pX2, pY2, pX3, pY3, 128, 128, 118, 118, 2, 2);
    }
    // Level 3: 64 -> out 54, last (ssim map), no pool. Tiles 64x12.
    {
        dim3 grid(1 * 5, NC, NB);      // tilesY=5 (5*12=60)
        ssim_level_kernel<64, 12, true, false, 12><<<grid, 64>>>(
            pX3, pY3, nullptr, nullptr, 64, 64, 54, 54, 1, 3);
    }

    finalize_kernel<<<1, 32>>>(out);
}